// round 11
// baseline (speedup 1.0000x reference)
#include <cuda_runtime.h>
#include <cuda_fp16.h>
#include <math.h>
#include <stdint.h>

#define B_ 256
#define D_ 128
#define C_ 100000
#define BC_ (B_ * C_)
#define SCALE_F 35.0f
#define COS_M 0.87758256189037271612f   // cos(0.5)
#define SIN_M 0.47942553860420300027f   // sin(0.5)

// ---------------- SMEM layout (bytes, dynamic) ------------------------------
#define OFF_INVF 0                     // 256 floats
#define OFF_INVW 1024                  // 128 floats
#define OFF_LAB  1536                  // 256 ints
#define OFF_FLAG 2560                  // 1 int (label-width flag)
#define OFF_A_HI 4096                  // 256 rows x 256B = 64 KB
#define OFF_A_LO (OFF_A_HI + 65536)
#define OFF_B_HI (OFF_A_LO + 65536)    // 128 rows x 256B = 32 KB
#define SMEM_TOTAL (OFF_B_HI + 32768)  // 167936 B -> 1 CTA/SM

// ---------------- PTX helpers (portable sm_80+) ------------------------------
__device__ __forceinline__ uint32_t smem_u32(const void* p) {
    uint32_t a;
    asm("{ .reg .u64 t; cvta.to.shared.u64 t, %1; cvt.u32.u64 %0, t; }" : "=r"(a) : "l"(p));
    return a;
}
__device__ __forceinline__ void ldsm4(uint32_t* r, uint32_t addr) {
    asm volatile("ldmatrix.sync.aligned.m8n8.x4.shared.b16 {%0,%1,%2,%3}, [%4];"
                 : "=r"(r[0]), "=r"(r[1]), "=r"(r[2]), "=r"(r[3]) : "r"(addr));
}
__device__ __forceinline__ void mma_f16(float* d, const uint32_t* a,
                                        uint32_t b0, uint32_t b1) {
    asm volatile("mma.sync.aligned.m16n8k16.row.col.f32.f16.f16.f32 "
                 "{%0,%1,%2,%3}, {%4,%5,%6,%7}, {%8,%9}, {%0,%1,%2,%3};"
                 : "+f"(d[0]), "+f"(d[1]), "+f"(d[2]), "+f"(d[3])
                 : "r"(a[0]), "r"(a[1]), "r"(a[2]), "r"(a[3]), "r"(b0), "r"(b1));
}

// ArcFace margin on the ground-truth cosine (algebraically = cos(acos x + m)).
__device__ __forceinline__ float arc_margin(float cosv) {
    float x = fminf(fmaxf(cosv, -1.0f), 1.0f);
    if (cosv > -COS_M) {
        float s = sqrtf(fmaxf(1.0f - x * x, 0.0f));
        return x * COS_M - SIN_M * s;
    }
    return x - 0.5f * SIN_M;
}

// ---------------------------------------------------------------------------
// Single fused kernel: feat prep + norms + HMMA GEMM + epilogue + gt margin.
// One CTA per 128-class tile (782 CTAs, 1/SM). Full 256-batch A tile.
// 8 warps in 4(m) x 2(n) grid; warp tile 64 x 64; d[4][8][4] accumulators.
// SMEM row-major 256B rows, 16B-chunk XOR-(row&7) swizzle (validated R6/R7).
// ---------------------------------------------------------------------------
__global__ __launch_bounds__(256, 1)
void arcface_fused_kernel(const float* __restrict__ feat,
                          const float* __restrict__ w,
                          const int* __restrict__ lab_raw,
                          float* __restrict__ out) {
    extern __shared__ char smem[];
    const uint32_t sb = smem_u32(smem);
    const int tid = threadIdx.x, warp = tid >> 5, lane = tid & 31;
    const int wm = warp >> 1, wn = warp & 1;
    const int cbase = blockIdx.x * 128;
    int* s_flag = reinterpret_cast<int*>(smem + OFF_FLAG);
    int* s_lab  = reinterpret_cast<int*>(smem + OFF_LAB);

    if (tid == 0) *s_flag = 1;          // assume int64 labels until disproven
    __syncthreads();                    // B1: flag visible before votes

    // ---- stage A (feat -> fp16 hi/lo) + invF; thread t owns batch row t ---
    {
        const float4* fr = reinterpret_cast<const float4*>(feat + tid * D_);
        uint32_t rb = (uint32_t)tid * 256u, rx = (uint32_t)(tid & 7);
        float s = 0.f;
        #pragma unroll
        for (int c = 0; c < 16; c++) {
            float4 v0 = fr[2 * c], v1 = fr[2 * c + 1];
            s += v0.x * v0.x + v0.y * v0.y + v0.z * v0.z + v0.w * v0.w;
            s += v1.x * v1.x + v1.y * v1.y + v1.z * v1.z + v1.w * v1.w;
            __half2 h0 = __floats2half2_rn(v0.x, v0.y);
            __half2 h1 = __floats2half2_rn(v0.z, v0.w);
            __half2 h2 = __floats2half2_rn(v1.x, v1.y);
            __half2 h3 = __floats2half2_rn(v1.z, v1.w);
            __half2 l0 = __floats2half2_rn(v0.x - __half2float(h0.x), v0.y - __half2float(h0.y));
            __half2 l1 = __floats2half2_rn(v0.z - __half2float(h1.x), v0.w - __half2float(h1.y));
            __half2 l2 = __floats2half2_rn(v1.x - __half2float(h2.x), v1.y - __half2float(h2.y));
            __half2 l3 = __floats2half2_rn(v1.z - __half2float(h3.x), v1.w - __half2float(h3.y));
            uint32_t sw = rb + (((uint32_t)c ^ rx) << 4);
            *reinterpret_cast<uint4*>(smem + OFF_A_HI + sw) =
                make_uint4(*reinterpret_cast<uint32_t*>(&h0), *reinterpret_cast<uint32_t*>(&h1),
                           *reinterpret_cast<uint32_t*>(&h2), *reinterpret_cast<uint32_t*>(&h3));
            *reinterpret_cast<uint4*>(smem + OFF_A_LO + sw) =
                make_uint4(*reinterpret_cast<uint32_t*>(&l0), *reinterpret_cast<uint32_t*>(&l1),
                           *reinterpret_cast<uint32_t*>(&l2), *reinterpret_cast<uint32_t*>(&l3));
        }
        *reinterpret_cast<float*>(smem + OFF_INVF + tid * 4) = rsqrtf(s);
    }

    // ---- stage W tile (fp16 hi) + per-class inv norms ---------------------
    {
        int r = tid >> 1, half = tid & 1;
        int cg = cbase + r; if (cg >= C_) cg = C_ - 1;
        const float4* wr = reinterpret_cast<const float4*>(w + (size_t)cg * D_ + half * 64);
        uint32_t rb = (uint32_t)r * 256u, rx = (uint32_t)(r & 7);
        float s = 0.f;
        #pragma unroll
        for (int i = 0; i < 8; i++) {
            float4 v0 = wr[2 * i], v1 = wr[2 * i + 1];
            s += v0.x * v0.x + v0.y * v0.y + v0.z * v0.z + v0.w * v0.w;
            s += v1.x * v1.x + v1.y * v1.y + v1.z * v1.z + v1.w * v1.w;
            __half2 h0 = __floats2half2_rn(v0.x, v0.y);
            __half2 h1 = __floats2half2_rn(v0.z, v0.w);
            __half2 h2 = __floats2half2_rn(v1.x, v1.y);
            __half2 h3 = __floats2half2_rn(v1.z, v1.w);
            uint32_t chunk = (uint32_t)(half * 8 + i);
            *reinterpret_cast<uint4*>(smem + OFF_B_HI + rb + ((chunk ^ rx) << 4)) =
                make_uint4(*reinterpret_cast<uint32_t*>(&h0), *reinterpret_cast<uint32_t*>(&h1),
                           *reinterpret_cast<uint32_t*>(&h2), *reinterpret_cast<uint32_t*>(&h3));
        }
        s += __shfl_xor_sync(0xffffffffu, s, 1);
        if (half == 0) *reinterpret_cast<float*>(smem + OFF_INVW + r * 4) = rsqrtf(s);
    }

    // ---- label width votes (int64 iff all high words zero) ----------------
    if (tid < 128 && lab_raw[2 * tid + 1] != 0) atomicExch(s_flag, 0);
    __syncthreads();                    // B2: staging + votes complete

    // ---- stage labels to smem --------------------------------------------
    {
        int is64 = *s_flag;
        s_lab[tid] = is64 ? lab_raw[2 * tid] : lab_raw[tid];
    }
    __syncthreads();                    // B3: labels visible before epilogue

    // ---- ldmatrix lane->address maps (validated R6/R7) --------------------
    const int a_row_in = lane & 15;
    const uint32_t a_sel = (uint32_t)(lane >> 4);
    const int b_cls_in = ((lane >> 4) << 3) | (lane & 7);
    const uint32_t b_sel = (uint32_t)((lane >> 3) & 1);

    uint32_t aAddrH[4], aAddrL[4], arx[4];
    #pragma unroll
    for (int fm = 0; fm < 4; fm++) {
        int arow = wm * 64 + fm * 16 + a_row_in;
        aAddrH[fm] = sb + OFF_A_HI + (uint32_t)arow * 256u;
        aAddrL[fm] = sb + OFF_A_LO + (uint32_t)arow * 256u;
        arx[fm] = (uint32_t)(arow & 7);
    }
    uint32_t bAddr[4], brx[4];
    #pragma unroll
    for (int j2 = 0; j2 < 4; j2++) {
        int brow = wn * 64 + j2 * 16 + b_cls_in;
        bAddr[j2] = sb + OFF_B_HI + (uint32_t)brow * 256u;
        brx[j2] = (uint32_t)(brow & 7);
    }

    float d[4][8][4];
    #pragma unroll
    for (int fm = 0; fm < 4; fm++)
        #pragma unroll
        for (int jn = 0; jn < 8; jn++)
            #pragma unroll
            for (int q = 0; q < 4; q++) d[fm][jn][q] = 0.f;

    // ---- mainloop: per k16 chunk, B loaded once, hi + lo passes -----------
    #pragma unroll
    for (int kk = 0; kk < 8; kk++) {
        uint32_t b[4][4];
        #pragma unroll
        for (int j2 = 0; j2 < 4; j2++) {
            uint32_t chunk = (uint32_t)kk * 2u + b_sel;
            ldsm4(b[j2], bAddr[j2] + ((chunk ^ brx[j2]) << 4));
        }
        uint32_t a[4][4];
        #pragma unroll
        for (int fm = 0; fm < 4; fm++) {
            uint32_t chunk = (uint32_t)kk * 2u + a_sel;
            ldsm4(a[fm], aAddrH[fm] + ((chunk ^ arx[fm]) << 4));
        }
        #pragma unroll
        for (int fm = 0; fm < 4; fm++)
            #pragma unroll
            for (int jn = 0; jn < 8; jn++)
                mma_f16(d[fm][jn], a[fm],
                        b[jn >> 1][(jn & 1) * 2], b[jn >> 1][(jn & 1) * 2 + 1]);
        #pragma unroll
        for (int fm = 0; fm < 4; fm++) {
            uint32_t chunk = (uint32_t)kk * 2u + a_sel;
            ldsm4(a[fm], aAddrL[fm] + ((chunk ^ arx[fm]) << 4));
        }
        #pragma unroll
        for (int fm = 0; fm < 4; fm++)
            #pragma unroll
            for (int jn = 0; jn < 8; jn++)
                mma_f16(d[fm][jn], a[fm],
                        b[jn >> 1][(jn & 1) * 2], b[jn >> 1][(jn & 1) * 2 + 1]);
    }

    // ---- epilogue (with inline gt-margin substitution) --------------------
    const int g = lane >> 2, t2 = (lane & 3) * 2;
    float* out_cos = out;
    float* out_mrg = out + BC_;
    float* out_ip  = out + 2 * BC_;

    #pragma unroll
    for (int fm = 0; fm < 4; fm++) {
        int bat0 = wm * 64 + fm * 16 + g;
        float if0 = *reinterpret_cast<float*>(smem + OFF_INVF + bat0 * 4);
        float if1 = *reinterpret_cast<float*>(smem + OFF_INVF + (bat0 + 8) * 4);
        int l0 = s_lab[bat0], l1 = s_lab[bat0 + 8];
        size_t ro0 = (size_t)bat0 * C_;
        size_t ro1 = (size_t)(bat0 + 8) * C_;
        #pragma unroll
        for (int jn = 0; jn < 8; jn++) {
            int cl = wn * 64 + jn * 8 + t2;
            int cls = cbase + cl;
            if (cls < C_) {
                float2 iw = *reinterpret_cast<float2*>(smem + OFF_INVW + cl * 4);
                float ip0 = d[fm][jn][0], ip1 = d[fm][jn][1];
                float ip2 = d[fm][jn][2], ip3 = d[fm][jn][3];
                float c0 = ip0 * if0 * iw.x, c1 = ip1 * if0 * iw.y;
                float c2 = ip2 * if1 * iw.x, c3 = ip3 * if1 * iw.y;
                float m0 = SCALE_F * c0, m1 = SCALE_F * c1;
                float m2 = SCALE_F * c2, m3 = SCALE_F * c3;
                // rare: this element pair touches a ground-truth column
                if ((l0 - cls) == 0 || (l0 - cls) == 1 || (l1 - cls) == 0 || (l1 - cls) == 1) {
                    if (l0 == cls)     m0 = SCALE_F * arc_margin(c0);
                    if (l0 == cls + 1) m1 = SCALE_F * arc_margin(c1);
                    if (l1 == cls)     m2 = SCALE_F * arc_margin(c2);
                    if (l1 == cls + 1) m3 = SCALE_F * arc_margin(c3);
                }
                *reinterpret_cast<float2*>(&out_ip[ro0 + cls])  = make_float2(ip0, ip1);
                *reinterpret_cast<float2*>(&out_ip[ro1 + cls])  = make_float2(ip2, ip3);
                *reinterpret_cast<float2*>(&out_cos[ro0 + cls]) = make_float2(c0, c1);
                *reinterpret_cast<float2*>(&out_cos[ro1 + cls]) = make_float2(c2, c3);
                *reinterpret_cast<float2*>(&out_mrg[ro0 + cls]) = make_float2(m0, m1);
                *reinterpret_cast<float2*>(&out_mrg[ro1 + cls]) = make_float2(m2, m3);
            }
        }
    }
}

// ---------------------------------------------------------------------------
extern "C" void kernel_launch(void* const* d_in, const int* in_sizes, int n_in,
                              void* d_out, int out_size) {
    const float* feat = (const float*)d_in[0];
    const float* w    = (const float*)d_in[1];
    const int*   lab  = (const int*)d_in[2];
    float* out = (float*)d_out;

    cudaFuncSetAttribute(arcface_fused_kernel,
                         cudaFuncAttributeMaxDynamicSharedMemorySize, SMEM_TOTAL);
    int ntiles = (C_ + 127) / 128;   // 782
    arcface_fused_kernel<<<ntiles, 256, SMEM_TOTAL>>>(feat, w, lab, out);
}

// round 12
// speedup vs baseline: 1.0183x; 1.0183x over previous
#include <cuda_runtime.h>
#include <cuda_fp16.h>
#include <math.h>
#include <stdint.h>

#define B_ 256
#define D_ 128
#define C_ 100000
#define BC_ (B_ * C_)
#define SCALE_F 35.0f

// ---------------- device globals (scratch; no allocs allowed) ---------------
__device__ float  g_invF[B_];
__device__ __half g_fhi[B_ * D_];
__device__ __half g_flo[B_ * D_];

// ---------------- SMEM layout (bytes, dynamic) ------------------------------
#define OFF_INVF 0                    // 256 floats
#define OFF_INVW 1024                 // 128 floats
#define OFF_A_HI 2048                 // 256 rows x 256B = 64 KB
#define OFF_A_LO (OFF_A_HI + 65536)
#define OFF_B_HI (OFF_A_LO + 65536)   // 128 rows x 256B = 32 KB
#define SMEM_TOTAL (OFF_B_HI + 32768) // 165888 B -> 1 CTA/SM

// ---------------- PTX helpers (portable sm_80+) ------------------------------
__device__ __forceinline__ uint32_t smem_u32(const void* p) {
    uint32_t a;
    asm("{ .reg .u64 t; cvta.to.shared.u64 t, %1; cvt.u32.u64 %0, t; }" : "=r"(a) : "l"(p));
    return a;
}
__device__ __forceinline__ void ldsm4(uint32_t* r, uint32_t addr) {
    asm volatile("ldmatrix.sync.aligned.m8n8.x4.shared.b16 {%0,%1,%2,%3}, [%4];"
                 : "=r"(r[0]), "=r"(r[1]), "=r"(r[2]), "=r"(r[3]) : "r"(addr));
}
__device__ __forceinline__ void mma_f16(float* d, const uint32_t* a,
                                        uint32_t b0, uint32_t b1) {
    asm volatile("mma.sync.aligned.m16n8k16.row.col.f32.f16.f16.f32 "
                 "{%0,%1,%2,%3}, {%4,%5,%6,%7}, {%8,%9}, {%0,%1,%2,%3};"
                 : "+f"(d[0]), "+f"(d[1]), "+f"(d[2]), "+f"(d[3])
                 : "r"(a[0]), "r"(a[1]), "r"(a[2]), "r"(a[3]), "r"(b0), "r"(b1));
}

// ---------------------------------------------------------------------------
// Kernel 1: feature prep — invF + fp16 hi/lo split. 32 blocks x 256 thr.
// ---------------------------------------------------------------------------
__global__ void prep_feat_kernel(const float* __restrict__ feat) {
    int warp = threadIdx.x >> 5, lane = threadIdx.x & 31;
    int row = blockIdx.x * 8 + warp;
    float4 v = *reinterpret_cast<const float4*>(&feat[row * D_ + lane * 4]);
    float s = v.x * v.x + v.y * v.y + v.z * v.z + v.w * v.w;
    #pragma unroll
    for (int o = 16; o > 0; o >>= 1) s += __shfl_xor_sync(0xffffffffu, s, o);

    __half2 h0 = __floats2half2_rn(v.x, v.y);
    __half2 h1 = __floats2half2_rn(v.z, v.w);
    __half2 l0 = __floats2half2_rn(v.x - __half2float(h0.x), v.y - __half2float(h0.y));
    __half2 l1 = __floats2half2_rn(v.z - __half2float(h1.x), v.w - __half2float(h1.y));
    *reinterpret_cast<uint2*>(&g_fhi[row * D_ + lane * 4]) =
        make_uint2(*reinterpret_cast<uint32_t*>(&h0), *reinterpret_cast<uint32_t*>(&h1));
    *reinterpret_cast<uint2*>(&g_flo[row * D_ + lane * 4]) =
        make_uint2(*reinterpret_cast<uint32_t*>(&l0), *reinterpret_cast<uint32_t*>(&l1));
    if (lane == 0) g_invF[row] = rsqrtf(s);
}

// ---------------------------------------------------------------------------
// Kernel 2: HMMA GEMM + epilogue. 512 threads (16 warps), 1 CTA/SM.
// One CTA per 128-class tile (782 CTAs). Full 256-batch A tile.
// Warp grid 8(m) x 2(n); warp tile 32 x 64; d[2][8][4] = 64 accum regs.
// SMEM row-major 256B rows, 16B-chunk XOR-(row&7) swizzle (validated R6/R7).
// ---------------------------------------------------------------------------
__global__ __launch_bounds__(512, 1)
void arcface_hmma_kernel(const float* __restrict__ w, float* __restrict__ out) {
    extern __shared__ char smem[];
    const uint32_t sb = smem_u32(smem);
    const int tid = threadIdx.x, warp = tid >> 5, lane = tid & 31;
    const int wm = warp >> 1, wn = warp & 1;
    const int cbase = blockIdx.x * 128;

    // ---- stage invF -------------------------------------------------------
    if (tid < 256) *reinterpret_cast<float*>(smem + OFF_INVF + tid * 4) = g_invF[tid];

    // ---- stage A: row = tid&255, hi/lo = tid>>8; 16 x 16B chunks ----------
    {
        int row = tid & 255, which = tid >> 8;
        const __half* src = (which ? g_flo : g_fhi) + row * D_;
        char* dstbase = smem + (which ? OFF_A_LO : OFF_A_HI);
        const uint4* sp = reinterpret_cast<const uint4*>(src);
        uint32_t rb = (uint32_t)row * 256u, rx = (uint32_t)(row & 7);
        #pragma unroll
        for (int c = 0; c < 16; c++)
            *reinterpret_cast<uint4*>(dstbase + rb + (((uint32_t)c ^ rx) << 4)) = sp[c];
    }

    // ---- stage W tile (fp16 hi) + per-class inv norms: 4 thr per class ----
    {
        int r = tid >> 2, q = tid & 3;
        int cg = cbase + r; if (cg >= C_) cg = C_ - 1;
        const float4* wr = reinterpret_cast<const float4*>(w + (size_t)cg * D_ + q * 32);
        uint32_t rb = (uint32_t)r * 256u, rx = (uint32_t)(r & 7);
        float s = 0.f;
        #pragma unroll
        for (int i = 0; i < 4; i++) {
            float4 v0 = wr[2 * i], v1 = wr[2 * i + 1];
            s += v0.x * v0.x + v0.y * v0.y + v0.z * v0.z + v0.w * v0.w;
            s += v1.x * v1.x + v1.y * v1.y + v1.z * v1.z + v1.w * v1.w;
            __half2 h0 = __floats2half2_rn(v0.x, v0.y);
            __half2 h1 = __floats2half2_rn(v0.z, v0.w);
            __half2 h2 = __floats2half2_rn(v1.x, v1.y);
            __half2 h3 = __floats2half2_rn(v1.z, v1.w);
            uint32_t chunk = (uint32_t)(q * 4 + i);
            *reinterpret_cast<uint4*>(smem + OFF_B_HI + rb + ((chunk ^ rx) << 4)) =
                make_uint4(*reinterpret_cast<uint32_t*>(&h0), *reinterpret_cast<uint32_t*>(&h1),
                           *reinterpret_cast<uint32_t*>(&h2), *reinterpret_cast<uint32_t*>(&h3));
        }
        s += __shfl_xor_sync(0xffffffffu, s, 1);
        s += __shfl_xor_sync(0xffffffffu, s, 2);
        if (q == 0) *reinterpret_cast<float*>(smem + OFF_INVW + r * 4) = rsqrtf(s);
    }

    __syncthreads();

    // ---- ldmatrix lane->address maps (validated R6/R7) --------------------
    const int a_row_in = lane & 15;
    const uint32_t a_sel = (uint32_t)(lane >> 4);
    const int b_cls_in = ((lane >> 4) << 3) | (lane & 7);
    const uint32_t b_sel = (uint32_t)((lane >> 3) & 1);

    uint32_t aAddrH[2], aAddrL[2], arx[2];
    #pragma unroll
    for (int fm = 0; fm < 2; fm++) {
        int arow = wm * 32 + fm * 16 + a_row_in;
        aAddrH[fm] = sb + OFF_A_HI + (uint32_t)arow * 256u;
        aAddrL[fm] = sb + OFF_A_LO + (uint32_t)arow * 256u;
        arx[fm] = (uint32_t)(arow & 7);
    }
    uint32_t bAddr[4], brx[4];
    #pragma unroll
    for (int j2 = 0; j2 < 4; j2++) {
        int brow = wn * 64 + j2 * 16 + b_cls_in;
        bAddr[j2] = sb + OFF_B_HI + (uint32_t)brow * 256u;
        brx[j2] = (uint32_t)(brow & 7);
    }

    float d[2][8][4];
    #pragma unroll
    for (int fm = 0; fm < 2; fm++)
        #pragma unroll
        for (int jn = 0; jn < 8; jn++)
            #pragma unroll
            for (int q = 0; q < 4; q++) d[fm][jn][q] = 0.f;

    // ---- mainloop: per k16 chunk, B loaded once, hi + lo passes -----------
    #pragma unroll
    for (int kk = 0; kk < 8; kk++) {
        uint32_t b[4][4];
        #pragma unroll
        for (int j2 = 0; j2 < 4; j2++) {
            uint32_t chunk = (uint32_t)kk * 2u + b_sel;
            ldsm4(b[j2], bAddr[j2] + ((chunk ^ brx[j2]) << 4));
        }
        uint32_t a[2][4];
        #pragma unroll
        for (int fm = 0; fm < 2; fm++) {
            uint32_t chunk = (uint32_t)kk * 2u + a_sel;
            ldsm4(a[fm], aAddrH[fm] + ((chunk ^ arx[fm]) << 4));
        }
        #pragma unroll
        for (int fm = 0; fm < 2; fm++)
            #pragma unroll
            for (int jn = 0; jn < 8; jn++)
                mma_f16(d[fm][jn], a[fm],
                        b[jn >> 1][(jn & 1) * 2], b[jn >> 1][(jn & 1) * 2 + 1]);
        #pragma unroll
        for (int fm = 0; fm < 2; fm++) {
            uint32_t chunk = (uint32_t)kk * 2u + a_sel;
            ldsm4(a[fm], aAddrL[fm] + ((chunk ^ arx[fm]) << 4));
        }
        #pragma unroll
        for (int fm = 0; fm < 2; fm++)
            #pragma unroll
            for (int jn = 0; jn < 8; jn++)
                mma_f16(d[fm][jn], a[fm],
                        b[jn >> 1][(jn & 1) * 2], b[jn >> 1][(jn & 1) * 2 + 1]);
    }

    // ---- epilogue ---------------------------------------------------------
    const int g = lane >> 2, t2 = (lane & 3) * 2;
    float* out_cos = out;
    float* out_mrg = out + BC_;
    float* out_ip  = out + 2 * BC_;

    #pragma unroll
    for (int fm = 0; fm < 2; fm++) {
        int bat0 = wm * 32 + fm * 16 + g;
        float if0 = *reinterpret_cast<float*>(smem + OFF_INVF + bat0 * 4);
        float if1 = *reinterpret_cast<float*>(smem + OFF_INVF + (bat0 + 8) * 4);
        size_t ro0 = (size_t)bat0 * C_;
        size_t ro1 = (size_t)(bat0 + 8) * C_;
        #pragma unroll
        for (int jn = 0; jn < 8; jn++) {
            int cl = wn * 64 + jn * 8 + t2;
            int cls = cbase + cl;
            if (cls < C_) {
                float2 iw = *reinterpret_cast<float2*>(smem + OFF_INVW + cl * 4);
                float ip0 = d[fm][jn][0], ip1 = d[fm][jn][1];
                float ip2 = d[fm][jn][2], ip3 = d[fm][jn][3];
                float c0 = ip0 * if0 * iw.x, c1 = ip1 * if0 * iw.y;
                float c2 = ip2 * if1 * iw.x, c3 = ip3 * if1 * iw.y;
                *reinterpret_cast<float2*>(&out_ip[ro0 + cls])  = make_float2(ip0, ip1);
                *reinterpret_cast<float2*>(&out_ip[ro1 + cls])  = make_float2(ip2, ip3);
                *reinterpret_cast<float2*>(&out_cos[ro0 + cls]) = make_float2(c0, c1);
                *reinterpret_cast<float2*>(&out_cos[ro1 + cls]) = make_float2(c2, c3);
                *reinterpret_cast<float2*>(&out_mrg[ro0 + cls]) =
                    make_float2(SCALE_F * c0, SCALE_F * c1);
                *reinterpret_cast<float2*>(&out_mrg[ro1 + cls]) =
                    make_float2(SCALE_F * c2, SCALE_F * c3);
            }
        }
    }
}

// ---------------------------------------------------------------------------
// Kernel 3: ground-truth margin fixup (256 entries), float math.
// ---------------------------------------------------------------------------
__global__ void fix_gt_kernel(const int* __restrict__ lab_raw,
                              const float* __restrict__ out_cos,
                              float* __restrict__ out_mrg) {
    __shared__ int s_is64;
    int tid = threadIdx.x;
    if (tid == 0) s_is64 = 1;
    __syncthreads();
    if (tid < 128 && lab_raw[2 * tid + 1] != 0) atomicExch(&s_is64, 0);
    __syncthreads();

    int c = s_is64 ? lab_raw[2 * tid] : lab_raw[tid];
    size_t idx = (size_t)tid * C_ + c;
    float cg = out_cos[idx];

    float x = fminf(fmaxf(cg, -1.0f), 1.0f);
    const float thresh = -0.87758256189037271612f;     // -cos(0.5)
    float m;
    if (cg > thresh) m = cosf(acosf(x) + 0.5f);
    else             m = x - 0.5f * 0.47942553860420300027f;  // x - 0.5*sin(0.5)
    out_mrg[idx] = SCALE_F * m;
}

// ---------------------------------------------------------------------------
extern "C" void kernel_launch(void* const* d_in, const int* in_sizes, int n_in,
                              void* d_out, int out_size) {
    const float* feat = (const float*)d_in[0];
    const float* w    = (const float*)d_in[1];
    const int*   lab  = (const int*)d_in[2];
    float* out = (float*)d_out;

    prep_feat_kernel<<<32, 256>>>(feat);

    cudaFuncSetAttribute(arcface_hmma_kernel,
                         cudaFuncAttributeMaxDynamicSharedMemorySize, SMEM_TOTAL);
    int ntiles = (C_ + 127) / 128;   // 782
    arcface_hmma_kernel<<<ntiles, 512, SMEM_TOTAL>>>(w, out);

    fix_gt_kernel<<<1, 256>>>(lab, out, out + BC_);
}

// round 13
// speedup vs baseline: 1.1234x; 1.1032x over previous
#include <cuda_runtime.h>
#include <cuda_fp16.h>
#include <math.h>
#include <stdint.h>

#define B_ 256
#define D_ 128
#define C_ 100000
#define BC_ (B_ * C_)
#define SCALE_F 35.0f
#define COS_M 0.87758256189037271612f   // cos(0.5)
#define SIN_M 0.47942553860420300027f   // sin(0.5)

// ---------------- device globals (scratch; no allocs allowed) ---------------
__device__ float  g_invF[B_];
__device__ __half g_fhi[B_ * D_];
__device__ __half g_flo[B_ * D_];

// ---------------- SMEM layout (bytes, dynamic) ------------------------------
#define OFF_INVF 0                     // 256 floats
#define OFF_INVW 1024                  // 128 floats
#define OFF_LAB  1536                  // 256 ints
#define OFF_FLAG 2560                  // 1 int
#define OFF_A_HI 4096                  // 256 rows x 256B = 64 KB
#define OFF_A_LO (OFF_A_HI + 65536)
#define OFF_B_HI (OFF_A_LO + 65536)    // 128 rows x 256B = 32 KB
#define SMEM_TOTAL (OFF_B_HI + 32768)  // 167936 B -> 1 CTA/SM

// ---------------- PTX helpers (portable sm_80+) ------------------------------
__device__ __forceinline__ uint32_t smem_u32(const void* p) {
    uint32_t a;
    asm("{ .reg .u64 t; cvta.to.shared.u64 t, %1; cvt.u32.u64 %0, t; }" : "=r"(a) : "l"(p));
    return a;
}
__device__ __forceinline__ void ldsm4(uint32_t* r, uint32_t addr) {
    asm volatile("ldmatrix.sync.aligned.m8n8.x4.shared.b16 {%0,%1,%2,%3}, [%4];"
                 : "=r"(r[0]), "=r"(r[1]), "=r"(r[2]), "=r"(r[3]) : "r"(addr));
}
__device__ __forceinline__ void mma_f16(float* d, const uint32_t* a,
                                        uint32_t b0, uint32_t b1) {
    asm volatile("mma.sync.aligned.m16n8k16.row.col.f32.f16.f16.f32 "
                 "{%0,%1,%2,%3}, {%4,%5,%6,%7}, {%8,%9}, {%0,%1,%2,%3};"
                 : "+f"(d[0]), "+f"(d[1]), "+f"(d[2]), "+f"(d[3])
                 : "r"(a[0]), "r"(a[1]), "r"(a[2]), "r"(a[3]), "r"(b0), "r"(b1));
}
__device__ __forceinline__ void cp_async16(uint32_t dst, const void* src) {
    asm volatile("cp.async.cg.shared.global [%0], [%1], 16;"
                 :: "r"(dst), "l"(src) : "memory");
}
__device__ __forceinline__ void cp_async_commit_wait() {
    asm volatile("cp.async.commit_group;" ::: "memory");
    asm volatile("cp.async.wait_group 0;" ::: "memory");
}

// ArcFace margin on the gt cosine (algebraically = cos(acos x + m)).
__device__ __forceinline__ float arc_margin(float cosv) {
    float x = fminf(fmaxf(cosv, -1.0f), 1.0f);
    if (cosv > -COS_M) {
        float s = sqrtf(fmaxf(1.0f - x * x, 0.0f));
        return x * COS_M - SIN_M * s;
    }
    return x - 0.5f * SIN_M;
}

// ---------------------------------------------------------------------------
// Kernel 1: feature prep — invF + fp16 hi/lo split. 32 blocks x 256 thr.
// ---------------------------------------------------------------------------
__global__ void prep_feat_kernel(const float* __restrict__ feat) {
    int warp = threadIdx.x >> 5, lane = threadIdx.x & 31;
    int row = blockIdx.x * 8 + warp;
    float4 v = *reinterpret_cast<const float4*>(&feat[row * D_ + lane * 4]);
    float s = v.x * v.x + v.y * v.y + v.z * v.z + v.w * v.w;
    #pragma unroll
    for (int o = 16; o > 0; o >>= 1) s += __shfl_xor_sync(0xffffffffu, s, o);

    __half2 h0 = __floats2half2_rn(v.x, v.y);
    __half2 h1 = __floats2half2_rn(v.z, v.w);
    __half2 l0 = __floats2half2_rn(v.x - __half2float(h0.x), v.y - __half2float(h0.y));
    __half2 l1 = __floats2half2_rn(v.z - __half2float(h1.x), v.w - __half2float(h1.y));
    *reinterpret_cast<uint2*>(&g_fhi[row * D_ + lane * 4]) =
        make_uint2(*reinterpret_cast<uint32_t*>(&h0), *reinterpret_cast<uint32_t*>(&h1));
    *reinterpret_cast<uint2*>(&g_flo[row * D_ + lane * 4]) =
        make_uint2(*reinterpret_cast<uint32_t*>(&l0), *reinterpret_cast<uint32_t*>(&l1));
    if (lane == 0) g_invF[row] = rsqrtf(s);
}

// ---------------------------------------------------------------------------
// Kernel 2: HMMA GEMM + epilogue (+ fused gt margin). Exact R7 GEMM shape:
// 256 threads, warp grid 4(m)x2(n), warp tile 64x64, d[4][8][4], 1 CTA/SM.
// A staged via coalesced cp.async; SMEM 256B rows, 16B-chunk XOR-(row&7).
// ---------------------------------------------------------------------------
__global__ __launch_bounds__(256, 1)
void arcface_hmma_kernel(const float* __restrict__ w,
                         const int* __restrict__ lab_raw,
                         float* __restrict__ out) {
    extern __shared__ char smem[];
    const uint32_t sb = smem_u32(smem);
    const int tid = threadIdx.x, warp = tid >> 5, lane = tid & 31;
    const int wm = warp >> 1, wn = warp & 1;
    const int cbase = blockIdx.x * 128;
    int* s_flag = reinterpret_cast<int*>(smem + OFF_FLAG);
    int* s_lab  = reinterpret_cast<int*>(smem + OFF_LAB);

    if (tid == 0) *s_flag = 1;
    // ---- stage invF -------------------------------------------------------
    *reinterpret_cast<float*>(smem + OFF_INVF + tid * 4) = g_invF[tid];

    // ---- stage A via coalesced cp.async: 8192 chunk-copies of 16B ---------
    // chunk id g = tid + 256*it: which = g>>12, row = (g>>4)&255, c = g&15.
    // Consecutive lanes -> consecutive chunks of one row (coalesced LDG side).
    {
        #pragma unroll
        for (int it = 0; it < 32; it++) {
            int gch = tid + 256 * it;
            int which = gch >> 12, row = (gch >> 4) & 255, c = gch & 15;
            const __half* src = (which ? g_flo : g_fhi) + row * D_ + c * 8;
            uint32_t dst = sb + (which ? OFF_A_LO : OFF_A_HI)
                         + (uint32_t)row * 256u
                         + (((uint32_t)c ^ (uint32_t)(row & 7)) << 4);
            cp_async16(dst, src);
        }
        cp_async_commit_wait();
    }

    // ---- stage W tile (fp16 hi) + per-class inv norms ---------------------
    {
        int r = tid >> 1, half = tid & 1;
        int cg = cbase + r; if (cg >= C_) cg = C_ - 1;
        const float4* wr = reinterpret_cast<const float4*>(w + (size_t)cg * D_ + half * 64);
        uint32_t rb = (uint32_t)r * 256u, rx = (uint32_t)(r & 7);
        float s = 0.f;
        #pragma unroll
        for (int i = 0; i < 8; i++) {
            float4 v0 = wr[2 * i], v1 = wr[2 * i + 1];
            s += v0.x * v0.x + v0.y * v0.y + v0.z * v0.z + v0.w * v0.w;
            s += v1.x * v1.x + v1.y * v1.y + v1.z * v1.z + v1.w * v1.w;
            __half2 h0 = __floats2half2_rn(v0.x, v0.y);
            __half2 h1 = __floats2half2_rn(v0.z, v0.w);
            __half2 h2 = __floats2half2_rn(v1.x, v1.y);
            __half2 h3 = __floats2half2_rn(v1.z, v1.w);
            uint32_t chunk = (uint32_t)(half * 8 + i);
            *reinterpret_cast<uint4*>(smem + OFF_B_HI + rb + ((chunk ^ rx) << 4)) =
                make_uint4(*reinterpret_cast<uint32_t*>(&h0), *reinterpret_cast<uint32_t*>(&h1),
                           *reinterpret_cast<uint32_t*>(&h2), *reinterpret_cast<uint32_t*>(&h3));
        }
        s += __shfl_xor_sync(0xffffffffu, s, 1);
        if (half == 0) *reinterpret_cast<float*>(smem + OFF_INVW + r * 4) = rsqrtf(s);
    }

    // ---- label width votes (flag written pre-staging; staged work between) -
    __syncthreads();                      // flag init + staging visible
    if (tid < 128 && lab_raw[2 * tid + 1] != 0) atomicExch(s_flag, 0);
    __syncthreads();
    s_lab[tid] = (*s_flag) ? lab_raw[2 * tid] : lab_raw[tid];
    __syncthreads();

    // ---- ldmatrix lane->address maps (validated R6/R7) --------------------
    const int a_row_in = lane & 15;
    const uint32_t a_sel = (uint32_t)(lane >> 4);
    const int b_cls_in = ((lane >> 4) << 3) | (lane & 7);
    const uint32_t b_sel = (uint32_t)((lane >> 3) & 1);

    uint32_t aAddrH[4], aAddrL[4], arx[4];
    #pragma unroll
    for (int fm = 0; fm < 4; fm++) {
        int arow = wm * 64 + fm * 16 + a_row_in;
        aAddrH[fm] = sb + OFF_A_HI + (uint32_t)arow * 256u;
        aAddrL[fm] = sb + OFF_A_LO + (uint32_t)arow * 256u;
        arx[fm] = (uint32_t)(arow & 7);
    }
    uint32_t bAddr[4], brx[4];
    #pragma unroll
    for (int j2 = 0; j2 < 4; j2++) {
        int brow = wn * 64 + j2 * 16 + b_cls_in;
        bAddr[j2] = sb + OFF_B_HI + (uint32_t)brow * 256u;
        brx[j2] = (uint32_t)(brow & 7);
    }

    float d[4][8][4];
    #pragma unroll
    for (int fm = 0; fm < 4; fm++)
        #pragma unroll
        for (int jn = 0; jn < 8; jn++)
            #pragma unroll
            for (int q = 0; q < 4; q++) d[fm][jn][q] = 0.f;

    // ---- mainloop (exact R7): per k16 chunk, B once, hi + lo passes -------
    #pragma unroll
    for (int kk = 0; kk < 8; kk++) {
        uint32_t b[4][4];
        #pragma unroll
        for (int j2 = 0; j2 < 4; j2++) {
            uint32_t chunk = (uint32_t)kk * 2u + b_sel;
            ldsm4(b[j2], bAddr[j2] + ((chunk ^ brx[j2]) << 4));
        }
        uint32_t a[4][4];
        #pragma unroll
        for (int fm = 0; fm < 4; fm++) {
            uint32_t chunk = (uint32_t)kk * 2u + a_sel;
            ldsm4(a[fm], aAddrH[fm] + ((chunk ^ arx[fm]) << 4));
        }
        #pragma unroll
        for (int fm = 0; fm < 4; fm++)
            #pragma unroll
            for (int jn = 0; jn < 8; jn++)
                mma_f16(d[fm][jn], a[fm],
                        b[jn >> 1][(jn & 1) * 2], b[jn >> 1][(jn & 1) * 2 + 1]);
        #pragma unroll
        for (int fm = 0; fm < 4; fm++) {
            uint32_t chunk = (uint32_t)kk * 2u + a_sel;
            ldsm4(a[fm], aAddrL[fm] + ((chunk ^ arx[fm]) << 4));
        }
        #pragma unroll
        for (int fm = 0; fm < 4; fm++)
            #pragma unroll
            for (int jn = 0; jn < 8; jn++)
                mma_f16(d[fm][jn], a[fm],
                        b[jn >> 1][(jn & 1) * 2], b[jn >> 1][(jn & 1) * 2 + 1]);
    }

    // ---- epilogue with inline gt-margin substitution ----------------------
    const int g = lane >> 2, t2 = (lane & 3) * 2;
    float* out_cos = out;
    float* out_mrg = out + BC_;
    float* out_ip  = out + 2 * BC_;

    #pragma unroll
    for (int fm = 0; fm < 4; fm++) {
        int bat0 = wm * 64 + fm * 16 + g;
        float if0 = *reinterpret_cast<float*>(smem + OFF_INVF + bat0 * 4);
        float if1 = *reinterpret_cast<float*>(smem + OFF_INVF + (bat0 + 8) * 4);
        int l0 = s_lab[bat0], l1 = s_lab[bat0 + 8];
        size_t ro0 = (size_t)bat0 * C_;
        size_t ro1 = (size_t)(bat0 + 8) * C_;
        #pragma unroll
        for (int jn = 0; jn < 8; jn++) {
            int cl = wn * 64 + jn * 8 + t2;
            int cls = cbase + cl;
            if (cls < C_) {
                float2 iw = *reinterpret_cast<float2*>(smem + OFF_INVW + cl * 4);
                float ip0 = d[fm][jn][0], ip1 = d[fm][jn][1];
                float ip2 = d[fm][jn][2], ip3 = d[fm][jn][3];
                float c0 = ip0 * if0 * iw.x, c1 = ip1 * if0 * iw.y;
                float c2 = ip2 * if1 * iw.x, c3 = ip3 * if1 * iw.y;
                float m0 = SCALE_F * c0, m1 = SCALE_F * c1;
                float m2 = SCALE_F * c2, m3 = SCALE_F * c3;
                unsigned hit = ((unsigned)(l0 - cls) <= 1u) | ((unsigned)(l1 - cls) <= 1u);
                if (hit) {                                  // 256 hits / 25.6M
                    if (l0 == cls)     m0 = SCALE_F * arc_margin(c0);
                    if (l0 == cls + 1) m1 = SCALE_F * arc_margin(c1);
                    if (l1 == cls)     m2 = SCALE_F * arc_margin(c2);
                    if (l1 == cls + 1) m3 = SCALE_F * arc_margin(c3);
                }
                *reinterpret_cast<float2*>(&out_ip[ro0 + cls])  = make_float2(ip0, ip1);
                *reinterpret_cast<float2*>(&out_ip[ro1 + cls])  = make_float2(ip2, ip3);
                *reinterpret_cast<float2*>(&out_cos[ro0 + cls]) = make_float2(c0, c1);
                *reinterpret_cast<float2*>(&out_cos[ro1 + cls]) = make_float2(c2, c3);
                *reinterpret_cast<float2*>(&out_mrg[ro0 + cls]) = make_float2(m0, m1);
                *reinterpret_cast<float2*>(&out_mrg[ro1 + cls]) = make_float2(m2, m3);
            }
        }
    }
}

// ---------------------------------------------------------------------------
extern "C" void kernel_launch(void* const* d_in, const int* in_sizes, int n_in,
                              void* d_out, int out_size) {
    const float* feat = (const float*)d_in[0];
    const float* w    = (const float*)d_in[1];
    const int*   lab  = (const int*)d_in[2];
    float* out = (float*)d_out;

    prep_feat_kernel<<<32, 256>>>(feat);

    cudaFuncSetAttribute(arcface_hmma_kernel,
                         cudaFuncAttributeMaxDynamicSharedMemorySize, SMEM_TOTAL);
    int ntiles = (C_ + 127) / 128;   // 782
    arcface_hmma_kernel<<<ntiles, 256, SMEM_TOTAL>>>(w, lab, out);
}

// round 15
// speedup vs baseline: 1.5493x; 1.3792x over previous
#include <cuda_runtime.h>
#include <cuda_fp16.h>
#include <math.h>
#include <stdint.h>

#define B_ 256
#define D_ 128
#define C_ 100000
#define BC_ (B_ * C_)
#define SCALE_F 35.0f
#define COS_M 0.87758256189037271612f   // cos(0.5)
#define SIN_M 0.47942553860420300027f   // sin(0.5)

// ---------------- device globals (scratch; no allocs allowed) ---------------
__device__ float  g_invF[B_];
__device__ __half g_fhi[B_ * D_];

// ---------------- SMEM layout (bytes, dynamic) ------------------------------
// Per-CTA 68 KB -> 2 CTAs/SM.
#define OFF_INVF 0                     // 128 floats (this batch half)
#define OFF_INVW 512                   // 128 floats
#define OFF_LAB  1024                  // 128 ints
#define OFF_FLAG 1536                  // 1 int
#define OFF_A    2048                  // 128 rows x 256B = 32 KB
#define OFF_B    (OFF_A + 32768)       // 128 rows x 256B = 32 KB
#define SMEM_TOTAL (OFF_B + 32768)     // 67584 B

// ---------------- PTX helpers (portable sm_80+) ------------------------------
__device__ __forceinline__ uint32_t smem_u32(const void* p) {
    uint32_t a;
    asm("{ .reg .u64 t; cvta.to.shared.u64 t, %1; cvt.u32.u64 %0, t; }" : "=r"(a) : "l"(p));
    return a;
}
__device__ __forceinline__ void ldsm4(uint32_t* r, uint32_t addr) {
    asm volatile("ldmatrix.sync.aligned.m8n8.x4.shared.b16 {%0,%1,%2,%3}, [%4];"
                 : "=r"(r[0]), "=r"(r[1]), "=r"(r[2]), "=r"(r[3]) : "r"(addr));
}
__device__ __forceinline__ void mma_f16(float* d, const uint32_t* a,
                                        uint32_t b0, uint32_t b1) {
    asm volatile("mma.sync.aligned.m16n8k16.row.col.f32.f16.f16.f32 "
                 "{%0,%1,%2,%3}, {%4,%5,%6,%7}, {%8,%9}, {%0,%1,%2,%3};"
                 : "+f"(d[0]), "+f"(d[1]), "+f"(d[2]), "+f"(d[3])
                 : "r"(a[0]), "r"(a[1]), "r"(a[2]), "r"(a[3]), "r"(b0), "r"(b1));
}

// ArcFace margin on the gt cosine (algebraically = cos(acos x + m)).
__device__ __forceinline__ float arc_margin(float cosv) {
    float x = fminf(fmaxf(cosv, -1.0f), 1.0f);
    if (cosv > -COS_M) {
        float s = sqrtf(fmaxf(1.0f - x * x, 0.0f));
        return x * COS_M - SIN_M * s;
    }
    return x - 0.5f * SIN_M;
}

// ---------------------------------------------------------------------------
// Kernel 1: feature prep — invF + fp16 conversion. 32 blocks x 256 thr.
// ---------------------------------------------------------------------------
__global__ void prep_feat_kernel(const float* __restrict__ feat) {
    int warp = threadIdx.x >> 5, lane = threadIdx.x & 31;
    int row = blockIdx.x * 8 + warp;
    float4 v = *reinterpret_cast<const float4*>(&feat[row * D_ + lane * 4]);
    float s = v.x * v.x + v.y * v.y + v.z * v.z + v.w * v.w;
    #pragma unroll
    for (int o = 16; o > 0; o >>= 1) s += __shfl_xor_sync(0xffffffffu, s, o);

    __half2 h0 = __floats2half2_rn(v.x, v.y);
    __half2 h1 = __floats2half2_rn(v.z, v.w);
    *reinterpret_cast<uint2*>(&g_fhi[row * D_ + lane * 4]) =
        make_uint2(*reinterpret_cast<uint32_t*>(&h0), *reinterpret_cast<uint32_t*>(&h1));
    if (lane == 0) g_invF[row] = rsqrtf(s);
}

// ---------------------------------------------------------------------------
// Kernel 2: HMMA GEMM + epilogue (+ fused gt margin). Single-pass fp16.
// Output tile 128 batch x 128 classes per CTA; grid (782, 2) — y = batch half.
// 256 threads, 8 warps in 4(m) x 2(n); warp tile 32 x 64; d[2][8][4] = 64 regs.
// 2 CTAs/SM (68 KB smem, <=128 regs). SMEM 256B rows, 16B-chunk XOR-(row&7).
// ---------------------------------------------------------------------------
__global__ __launch_bounds__(256, 2)
void arcface_hmma_kernel(const float* __restrict__ w,
                         const int* __restrict__ lab_raw,
                         float* __restrict__ out) {
    extern __shared__ char smem[];
    const uint32_t sb = smem_u32(smem);
    const int tid = threadIdx.x, warp = tid >> 5, lane = tid & 31;
    const int wm = warp >> 1, wn = warp & 1;
    const int cbase = blockIdx.x * 128;
    const int bbase = blockIdx.y * 128;
    int* s_flag = reinterpret_cast<int*>(smem + OFF_FLAG);
    int* s_lab  = reinterpret_cast<int*>(smem + OFF_LAB);

    if (tid == 0) *s_flag = 1;
    if (tid < 128) *reinterpret_cast<float*>(smem + OFF_INVF + tid * 4) = g_invF[bbase + tid];

    // ---- stage A (fp16 feat, this batch half): 2 threads per row ----------
    {
        int row = tid >> 1, half = tid & 1;                 // row 0..127
        const uint4* sp = reinterpret_cast<const uint4*>(g_fhi + (bbase + row) * D_ + half * 64);
        uint32_t rb = (uint32_t)row * 256u, rx = (uint32_t)(row & 7);
        #pragma unroll
        for (int c = 0; c < 8; c++) {
            uint32_t chunk = (uint32_t)(half * 8 + c);
            *reinterpret_cast<uint4*>(smem + OFF_A + rb + ((chunk ^ rx) << 4)) = sp[c];
        }
    }

    // ---- stage W tile (fp16) + per-class inv norms ------------------------
    {
        int r = tid >> 1, half = tid & 1;
        int cg = cbase + r; if (cg >= C_) cg = C_ - 1;
        const float4* wr = reinterpret_cast<const float4*>(w + (size_t)cg * D_ + half * 64);
        uint32_t rb = (uint32_t)r * 256u, rx = (uint32_t)(r & 7);
        float s = 0.f;
        #pragma unroll
        for (int i = 0; i < 8; i++) {
            float4 v0 = wr[2 * i], v1 = wr[2 * i + 1];
            s += v0.x * v0.x + v0.y * v0.y + v0.z * v0.z + v0.w * v0.w;
            s += v1.x * v1.x + v1.y * v1.y + v1.z * v1.z + v1.w * v1.w;
            __half2 h0 = __floats2half2_rn(v0.x, v0.y);
            __half2 h1 = __floats2half2_rn(v0.z, v0.w);
            __half2 h2 = __floats2half2_rn(v1.x, v1.y);
            __half2 h3 = __floats2half2_rn(v1.z, v1.w);
            uint32_t chunk = (uint32_t)(half * 8 + i);
            *reinterpret_cast<uint4*>(smem + OFF_B + rb + ((chunk ^ rx) << 4)) =
                make_uint4(*reinterpret_cast<uint32_t*>(&h0), *reinterpret_cast<uint32_t*>(&h1),
                           *reinterpret_cast<uint32_t*>(&h2), *reinterpret_cast<uint32_t*>(&h3));
        }
        s += __shfl_xor_sync(0xffffffffu, s, 1);
        if (half == 0) *reinterpret_cast<float*>(smem + OFF_INVW + r * 4) = rsqrtf(s);
    }

    // ---- label width votes (safe indices 0..255 for both widths) ----------
    __syncthreads();
    if (tid < 128 && lab_raw[2 * tid + 1] != 0) atomicExch(s_flag, 0);
    __syncthreads();
    if (tid < 128)
        s_lab[tid] = (*s_flag) ? lab_raw[2 * (bbase + tid)] : lab_raw[bbase + tid];
    __syncthreads();

    // ---- ldmatrix lane->address maps (validated R6/R7) --------------------
    const int a_row_in = lane & 15;
    const uint32_t a_sel = (uint32_t)(lane >> 4);
    const int b_cls_in = ((lane >> 4) << 3) | (lane & 7);
    const uint32_t b_sel = (uint32_t)((lane >> 3) & 1);

    uint32_t aAddr[2], arx[2];
    #pragma unroll
    for (int fm = 0; fm < 2; fm++) {
        int arow = wm * 32 + fm * 16 + a_row_in;
        aAddr[fm] = sb + OFF_A + (uint32_t)arow * 256u;
        arx[fm] = (uint32_t)(arow & 7);
    }
    uint32_t bAddr[4], brx[4];
    #pragma unroll
    for (int j2 = 0; j2 < 4; j2++) {
        int brow = wn * 64 + j2 * 16 + b_cls_in;
        bAddr[j2] = sb + OFF_B + (uint32_t)brow * 256u;
        brx[j2] = (uint32_t)(brow & 7);
    }

    float d[2][8][4];
    #pragma unroll
    for (int fm = 0; fm < 2; fm++)
        #pragma unroll
        for (int jn = 0; jn < 8; jn++)
            #pragma unroll
            for (int q = 0; q < 4; q++) d[fm][jn][q] = 0.f;

    // ---- mainloop: single fp16 pass, 16 MMAs per k16 chunk ----------------
    #pragma unroll
    for (int kk = 0; kk < 8; kk++) {
        uint32_t b[4][4];
        #pragma unroll
        for (int j2 = 0; j2 < 4; j2++) {
            uint32_t chunk = (uint32_t)kk * 2u + b_sel;
            ldsm4(b[j2], bAddr[j2] + ((chunk ^ brx[j2]) << 4));
        }
        uint32_t a[2][4];
        #pragma unroll
        for (int fm = 0; fm < 2; fm++) {
            uint32_t chunk = (uint32_t)kk * 2u + a_sel;
            ldsm4(a[fm], aAddr[fm] + ((chunk ^ arx[fm]) << 4));
        }
        #pragma unroll
        for (int fm = 0; fm < 2; fm++)
            #pragma unroll
            for (int jn = 0; jn < 8; jn++)
                mma_f16(d[fm][jn], a[fm],
                        b[jn >> 1][(jn & 1) * 2], b[jn >> 1][(jn & 1) * 2 + 1]);
    }

    // ---- epilogue with inline gt-margin substitution ----------------------
    const int g = lane >> 2, t2 = (lane & 3) * 2;
    float* out_cos = out;
    float* out_mrg = out + BC_;
    float* out_ip  = out + 2 * BC_;

    #pragma unroll
    for (int fm = 0; fm < 2; fm++) {
        int loc0 = wm * 32 + fm * 16 + g;                   // local batch row
        float if0 = *reinterpret_cast<float*>(smem + OFF_INVF + loc0 * 4);
        float if1 = *reinterpret_cast<float*>(smem + OFF_INVF + (loc0 + 8) * 4);
        int l0 = s_lab[loc0], l1 = s_lab[loc0 + 8];
        size_t ro0 = (size_t)(bbase + loc0) * C_;
        size_t ro1 = (size_t)(bbase + loc0 + 8) * C_;
        #pragma unroll
        for (int jn = 0; jn < 8; jn++) {
            int cl = wn * 64 + jn * 8 + t2;
            int cls = cbase + cl;
            if (cls < C_) {
                float2 iw = *reinterpret_cast<float2*>(smem + OFF_INVW + cl * 4);
                float ip0 = d[fm][jn][0], ip1 = d[fm][jn][1];
                float ip2 = d[fm][jn][2], ip3 = d[fm][jn][3];
                float c0 = ip0 * if0 * iw.x, c1 = ip1 * if0 * iw.y;
                float c2 = ip2 * if1 * iw.x, c3 = ip3 * if1 * iw.y;
                float m0 = SCALE_F * c0, m1 = SCALE_F * c1;
                float m2 = SCALE_F * c2, m3 = SCALE_F * c3;
                unsigned hit = ((unsigned)(l0 - cls) <= 1u) | ((unsigned)(l1 - cls) <= 1u);
                if (hit) {                                   // 256 hits / 25.6M
                    if (l0 == cls)     m0 = SCALE_F * arc_margin(c0);
                    if (l0 == cls + 1) m1 = SCALE_F * arc_margin(c1);
                    if (l1 == cls)     m2 = SCALE_F * arc_margin(c2);
                    if (l1 == cls + 1) m3 = SCALE_F * arc_margin(c3);
                }
                *reinterpret_cast<float2*>(&out_ip[ro0 + cls])  = make_float2(ip0, ip1);
                *reinterpret_cast<float2*>(&out_ip[ro1 + cls])  = make_float2(ip2, ip3);
                *reinterpret_cast<float2*>(&out_cos[ro0 + cls]) = make_float2(c0, c1);
                *reinterpret_cast<float2*>(&out_cos[ro1 + cls]) = make_float2(c2, c3);
                *reinterpret_cast<float2*>(&out_mrg[ro0 + cls]) = make_float2(m0, m1);
                *reinterpret_cast<float2*>(&out_mrg[ro1 + cls]) = make_float2(m2, m3);
            }
        }
    }
}

// ---------------------------------------------------------------------------
extern "C" void kernel_launch(void* const* d_in, const int* in_sizes, int n_in,
                              void* d_out, int out_size) {
    const float* feat = (const float*)d_in[0];
    const float* w    = (const float*)d_in[1];
    const int*   lab  = (const int*)d_in[2];
    float* out = (float*)d_out;

    prep_feat_kernel<<<32, 256>>>(feat);

    cudaFuncSetAttribute(arcface_hmma_kernel,
                         cudaFuncAttributeMaxDynamicSharedMemorySize, SMEM_TOTAL);
    dim3 grid((C_ + 127) / 128, 2);   // 782 x 2
    arcface_hmma_kernel<<<grid, 256, SMEM_TOTAL>>>(w, lab, out);
}